// round 14
// baseline (speedup 1.0000x reference)
#include <cuda_runtime.h>
#include <cuda_fp16.h>
#include <cstdint>

#define Nn 4096
#define Cc 1000
#define Aa 2048
#define Cpad 1024

#define BM 128
#define BN 128
#define NKT (Aa / 32)              // 64 k-steps of 32 fp16
#define TILE_B 8192                // 128 rows x 64B (32 fp16)
#define NMATS 5                    // Fh, C, G | W, W2
#define STAGE_B (NMATS * TILE_B)   // 40960
#define NST 3
#define SMEM_DYN (NST * STAGE_B)   // 122880

// -------- device scratch --------
__device__ __half g_Fh[(size_t)Nn * Aa];
__device__ __half g_C [(size_t)Nn * Aa];
__device__ __half g_G [(size_t)Nn * Aa];    // -2*cv*Wy
__device__ __half g_W [(size_t)Cpad * Aa];
__device__ __half g_W2[(size_t)Cpad * Aa];
__device__ float g_t3[Nn];
__device__ float g_sum[Nn];                 // sum_c exp(aug)  (atomic)
__device__ float g_labv[Nn];                // aug at label column

// -------- helpers --------
__device__ __forceinline__ uint32_t smem_u32(const void* p) {
    return (uint32_t)__cvta_generic_to_shared(const_cast<void*>(p));
}
__device__ __forceinline__ void cp16(uint32_t s, const void* g) {
    asm volatile("cp.async.cg.shared.global [%0], [%1], 16;" :: "r"(s), "l"(g));
}
__device__ __forceinline__ void cp_commit() {
    asm volatile("cp.async.commit_group;" ::: "memory");
}
__device__ __forceinline__ void ldsm4(uint32_t* r, uint32_t addr) {
    asm volatile("ldmatrix.sync.aligned.m8n8.x4.shared.b16 {%0,%1,%2,%3}, [%4];"
                 : "=r"(r[0]), "=r"(r[1]), "=r"(r[2]), "=r"(r[3]) : "r"(addr));
}
__device__ __forceinline__ void mma_f16(float* d, const uint32_t* a, uint32_t b0, uint32_t b1) {
    asm volatile(
        "mma.sync.aligned.m16n8k16.row.col.f32.f16.f16.f32 "
        "{%0,%1,%2,%3}, {%4,%5,%6,%7}, {%8,%9}, {%0,%1,%2,%3};"
        : "+f"(d[0]), "+f"(d[1]), "+f"(d[2]), "+f"(d[3])
        : "r"(a[0]), "r"(a[1]), "r"(a[2]), "r"(a[3]), "r"(b0), "r"(b1));
}
__device__ __forceinline__ int load_label(const int* labels, int n) {
    int lab = labels[n];
    return lab < 0 ? 0 : (lab >= Cc ? Cc - 1 : lab);
}
// swizzled offset in a tile with 64B rows (4 x 16B chunks per row)
__device__ __forceinline__ uint32_t tswz(int row, int c16) {
    return (uint32_t)(row * 64 + ((c16 ^ ((row >> 1) & 3)) << 4));
}
__device__ __forceinline__ uint32_t h2(float a, float b) {
    __half2 h = __floats2half2_rn(a, b);
    return *(uint32_t*)&h;
}
__device__ __forceinline__ uint2 h4(float4 v) {
    return make_uint2(h2(v.x, v.y), h2(v.z, v.w));
}

// ---------------- prep (float4-vectorized; also zeroes g_sum) ----------------
__global__ void prep_all(const float* __restrict__ F, const float* __restrict__ CV,
                         const int* __restrict__ labels, const float* __restrict__ W) {
    const int b = blockIdx.x;
    const int tid = threadIdx.x;
    if (b < Cpad) {
        if (b < 16) {
            g_sum[b * 256 + tid] = 0.f;
        }
        const int c = b;
        uint2* w  = (uint2*)(g_W  + (size_t)c * Aa);   // 4 fp16 per uint2
        uint2* w2 = (uint2*)(g_W2 + (size_t)c * Aa);
        if (c >= Cc) {
            const uint2 z = make_uint2(0u, 0u);
            for (int q = tid; q < Aa / 4; q += 256) { w[q] = z; w2[q] = z; }
            return;
        }
        const float4* wrow = (const float4*)(W + (size_t)c * Aa);
#pragma unroll 2
        for (int q = tid; q < Aa / 4; q += 256) {
            float4 v = wrow[q];
            w[q]  = h4(v);
            w2[q] = h4(make_float4(v.x * v.x, v.y * v.y, v.z * v.z, v.w * v.w));
        }
    } else {
        const int n = b - Cpad;
        const int lab = load_label(labels, n);
        const float4* frow = (const float4*)(F  + (size_t)n * Aa);
        const float4* crow = (const float4*)(CV + (size_t)n * Aa);
        const float4* wrow = (const float4*)(W  + (size_t)lab * Aa);
        uint2* fh = (uint2*)(g_Fh + (size_t)n * Aa);
        uint2* cb = (uint2*)(g_C + (size_t)n * Aa);
        uint2* gb = (uint2*)(g_G + (size_t)n * Aa);

        float t3 = 0.f;
#pragma unroll 2
        for (int q = tid; q < Aa / 4; q += 256) {
            float4 f = frow[q];
            float4 cv = crow[q];
            float4 wy = wrow[q];
            fh[q] = h4(f);
            cb[q] = h4(cv);
            float gx = cv.x * wy.x, gy = cv.y * wy.y;
            float gz = cv.z * wy.z, gw = cv.w * wy.w;
            gb[q] = h4(make_float4(-2.f * gx, -2.f * gy, -2.f * gz, -2.f * gw));
            t3 += gx * wy.x + gy * wy.y + gz * wy.z + gw * wy.w;
        }
        for (int o = 16; o; o >>= 1) t3 += __shfl_xor_sync(~0u, t3, o);
        __shared__ float ws[8];
        if ((tid & 31) == 0) ws[tid >> 5] = t3;
        __syncthreads();
        if (tid == 0) {
            float s = 0.f;
            for (int i = 0; i < 8; i++) s += ws[i];
            g_t3[n] = s;
        }
    }
}

// ---------------- fused triple GEMM + logsumexp epilogue (R11 config) ----------------
// accL = Fh.W -> logits ; accS = C.W2 + G.W -> sigma
__global__ __launch_bounds__(256, 1)
void gemm3h(const float* __restrict__ bias, const float* __restrict__ ratio_p,
            const int* __restrict__ labels, float* __restrict__ logits_out)
{
    extern __shared__ char smem[];
    const uint32_t sbase = smem_u32(smem);

    const int tid = threadIdx.x;
    const int lane = tid & 31;
    const int wid = tid >> 5;
    const int warp_m = wid >> 2;   // 0..1 : 64 rows
    const int warp_n = wid & 3;    // 0..3 : 32 cols
    const int bm = blockIdx.y * BM;
    const int bn = blockIdx.x * BN;

    const char* mp[NMATS];
    mp[0] = (const char*)g_Fh + (size_t)bm * 4096;
    mp[1] = (const char*)g_C  + (size_t)bm * 4096;
    mp[2] = (const char*)g_G  + (size_t)bm * 4096;
    mp[3] = (const char*)g_W  + (size_t)bn * 4096;
    mp[4] = (const char*)g_W2 + (size_t)bn * 4096;

    const int lrow = tid >> 2;          // 0..63
    const int lc16 = tid & 3;
    const uint32_t so0 = tswz(lrow, lc16);
    const uint32_t so1 = tswz(lrow + 64, lc16);
    const size_t go0 = (size_t)lrow * 4096 + lc16 * 16;
    const size_t go1 = go0 + (size_t)64 * 4096;

#define ISSUE(KT, S)                                                          \
    do {                                                                      \
        const size_t kb = (size_t)(KT) * 64;                                  \
        const uint32_t st_ = sbase + (uint32_t)(S) * STAGE_B;                 \
        _Pragma("unroll")                                                     \
        for (int m_ = 0; m_ < NMATS; m_++) {                                  \
            cp16(st_ + m_ * TILE_B + so0, mp[m_] + go0 + kb);                 \
            cp16(st_ + m_ * TILE_B + so1, mp[m_] + go1 + kb);                 \
        }                                                                     \
        cp_commit();                                                          \
    } while (0)

    float accL[4][4][4], accS[4][4][4];
#pragma unroll
    for (int i = 0; i < 4; i++)
#pragma unroll
        for (int j = 0; j < 4; j++)
#pragma unroll
            for (int e = 0; e < 4; e++) { accL[i][j][e] = 0.f; accS[i][j][e] = 0.f; }

    ISSUE(0, 0); ISSUE(1, 1);

    const int lr16 = lane & 15;
    const int lkhalf = lane >> 4;

    for (int kt = 0; kt < NKT; kt++) {
        if (kt == NKT - 1) { asm volatile("cp.async.wait_group 0;" ::: "memory"); }
        else               { asm volatile("cp.async.wait_group 1;" ::: "memory"); }
        __syncthreads();
        if (kt + 2 < NKT) ISSUE(kt + 2, (kt + 2) % NST);
        const uint32_t st = sbase + (uint32_t)(kt % NST) * STAGE_B;

#pragma unroll
        for (int k16 = 0; k16 < 2; k16++) {
            const int c16 = k16 * 2 + lkhalf;
            uint32_t bW[2][4], bW2[2][4];
#pragma unroll
            for (int np = 0; np < 2; np++) {
                const int r = warp_n * 32 + np * 16 + lr16;
                ldsm4(bW[np],  st + 3 * TILE_B + tswz(r, c16));
                ldsm4(bW2[np], st + 4 * TILE_B + tswz(r, c16));
            }
#pragma unroll
            for (int mt = 0; mt < 4; mt++) {
                uint32_t aF[4], aC[4], aG[4];
                const int r = warp_m * 64 + mt * 16 + lr16;
                ldsm4(aF, st + 0 * TILE_B + tswz(r, c16));
                ldsm4(aC, st + 1 * TILE_B + tswz(r, c16));
                ldsm4(aG, st + 2 * TILE_B + tswz(r, c16));
#pragma unroll
                for (int nt = 0; nt < 4; nt++) {
                    const int np = nt >> 1, sel = nt & 1;
                    const uint32_t w0 = bW[np][sel],  w1 = bW[np][sel + 2];
                    const uint32_t q0 = bW2[np][sel], q1 = bW2[np][sel + 2];
                    mma_f16(accL[mt][nt], aF, w0, w1);   // logits
                    mma_f16(accS[mt][nt], aC, q0, q1);   // t1
                    mma_f16(accS[mt][nt], aG, w0, w1);   // -2 t2
                }
            }
        }
    }
#undef ISSUE

    // ---------------- epilogue: logits store + fused logsumexp ----------------
    const float hr = 0.5f * (*ratio_p);
    const int r0 = lane >> 2;
    const int cq = (lane & 3) * 2;
#pragma unroll
    for (int mt = 0; mt < 4; mt++) {
        const int n0 = bm + warp_m * 64 + mt * 16 + r0;
        const int n1 = n0 + 8;
        const float t3a = g_t3[n0];
        const float t3b = g_t3[n1];
        const int lab0 = load_label(labels, n0);
        const int lab1 = load_label(labels, n1);
        float* lr0 = logits_out + (size_t)n0 * Cc;
        float* lr1 = logits_out + (size_t)n1 * Cc;
        float s0 = 0.f, s1 = 0.f;
#pragma unroll
        for (int nt = 0; nt < 4; nt++) {
            const int c = bn + warp_n * 32 + nt * 8 + cq;
            if (c < Cc) {
                const float2 bv = *(const float2*)(bias + c);
                const float* L = accL[mt][nt];
                const float* S = accS[mt][nt];
                const float l00 = L[0] + bv.x, l01 = L[1] + bv.y;
                const float l10 = L[2] + bv.x, l11 = L[3] + bv.y;
                lr0[c] = l00; lr0[c + 1] = l01;      // 4B-aligned base
                lr1[c] = l10; lr1[c + 1] = l11;
                const float a00 = l00 + hr * (S[0] + t3a);
                const float a01 = l01 + hr * (S[1] + t3a);
                const float a10 = l10 + hr * (S[2] + t3b);
                const float a11 = l11 + hr * (S[3] + t3b);
                s0 += expf(a00) + expf(a01);
                s1 += expf(a10) + expf(a11);
                if (c == lab0)     g_labv[n0] = a00;
                if (c + 1 == lab0) g_labv[n0] = a01;
                if (c == lab1)     g_labv[n1] = a10;
                if (c + 1 == lab1) g_labv[n1] = a11;
            }
        }
        s0 += __shfl_xor_sync(~0u, s0, 1); s0 += __shfl_xor_sync(~0u, s0, 2);
        s1 += __shfl_xor_sync(~0u, s1, 1); s1 += __shfl_xor_sync(~0u, s1, 2);
        if ((lane & 3) == 0) {
            atomicAdd(&g_sum[n0], s0);
            atomicAdd(&g_sum[n1], s1);
        }
    }
}

// ---------------- final: nll = log(sum) - labv ; mean ----------------
__global__ void finalize_kernel(float* __restrict__ out) {
    const int tid = threadIdx.x;
    float s = 0.f;
    for (int i = tid; i < Nn; i += 1024)
        s += logf(g_sum[i]) - g_labv[i];
    for (int o = 16; o; o >>= 1) s += __shfl_xor_sync(~0u, s, o);
    __shared__ float ws[32];
    if ((tid & 31) == 0) ws[tid >> 5] = s;
    __syncthreads();
    if (tid < 32) {
        float v = ws[tid];
        for (int o = 16; o; o >>= 1) v += __shfl_xor_sync(~0u, v, o);
        if (tid == 0) out[0] = v / (float)Nn;
    }
}

// ---------------- launch ----------------
extern "C" void kernel_launch(void* const* d_in, const int* in_sizes, int n_in,
                              void* d_out, int out_size) {
    const float* F      = (const float*)d_in[0];
    const int*   labels = (const int*)d_in[1];
    const float* CV     = (const float*)d_in[2];
    const float* ratio  = (const float*)d_in[3];
    const float* W      = (const float*)d_in[4];
    const float* bias   = (const float*)d_in[5];
    float* out = (float*)d_out;

    long long logits_off = (long long)out_size - (long long)Nn * Cc;
    if (logits_off < 0) logits_off = 0;
    float* logits_out = out + logits_off;

    static bool attr_set = false;
    if (!attr_set) {
        cudaFuncSetAttribute(gemm3h, cudaFuncAttributeMaxDynamicSharedMemorySize, SMEM_DYN);
        attr_set = true;
    }

    prep_all<<<Cpad + Nn, 256>>>(F, CV, labels, W);

    dim3 grid(Cpad / BN, Nn / BM);   // 8 x 32 = 256 CTAs
    gemm3h<<<grid, 256, SMEM_DYN>>>(bias, ratio, labels, logits_out);

    finalize_kernel<<<1, 1024>>>(out);
}

// round 15
// speedup vs baseline: 1.4958x; 1.4958x over previous
#include <cuda_runtime.h>
#include <cuda_fp16.h>
#include <cstdint>

#define Nn 4096
#define Cc 1000
#define Aa 2048
#define Cpad 1024

#define BM 128
#define BN 128
#define NKT (Aa / 32)              // 64 k-steps of 32 fp16
#define TILE_B 8192                // 128 rows x 64B (32 fp16)
#define NMATS 5                    // Fh, C, G | W, W2
#define STAGE_B (NMATS * TILE_B)   // 40960
#define NST 3
#define SMEM_DYN (NST * STAGE_B)   // 122880

// -------- device scratch --------
__device__ __half g_Fh[(size_t)Nn * Aa];
__device__ __half g_C [(size_t)Nn * Aa];
__device__ __half g_G [(size_t)Nn * Aa];    // -2*cv*Wy
__device__ __half g_W [(size_t)Cpad * Aa];
__device__ __half g_W2[(size_t)Cpad * Aa];
__device__ float g_t3[Nn];
__device__ float g_sum[Nn];                 // sum_c exp(aug)  (atomic)
__device__ float g_labv[Nn];                // aug at label column

// -------- helpers --------
__device__ __forceinline__ uint32_t smem_u32(const void* p) {
    return (uint32_t)__cvta_generic_to_shared(const_cast<void*>(p));
}
__device__ __forceinline__ void cp16(uint32_t s, const void* g) {
    asm volatile("cp.async.cg.shared.global [%0], [%1], 16;" :: "r"(s), "l"(g));
}
__device__ __forceinline__ void cp_commit() {
    asm volatile("cp.async.commit_group;" ::: "memory");
}
__device__ __forceinline__ void ldsm4(uint32_t* r, uint32_t addr) {
    asm volatile("ldmatrix.sync.aligned.m8n8.x4.shared.b16 {%0,%1,%2,%3}, [%4];"
                 : "=r"(r[0]), "=r"(r[1]), "=r"(r[2]), "=r"(r[3]) : "r"(addr));
}
__device__ __forceinline__ void mma_f16(float* d, const uint32_t* a, uint32_t b0, uint32_t b1) {
    asm volatile(
        "mma.sync.aligned.m16n8k16.row.col.f32.f16.f16.f32 "
        "{%0,%1,%2,%3}, {%4,%5,%6,%7}, {%8,%9}, {%0,%1,%2,%3};"
        : "+f"(d[0]), "+f"(d[1]), "+f"(d[2]), "+f"(d[3])
        : "r"(a[0]), "r"(a[1]), "r"(a[2]), "r"(a[3]), "r"(b0), "r"(b1));
}
__device__ __forceinline__ int load_label(const int* labels, int n) {
    int lab = labels[n];
    return lab < 0 ? 0 : (lab >= Cc ? Cc - 1 : lab);
}
// swizzled offset in a tile with 64B rows (4 x 16B chunks per row)
__device__ __forceinline__ uint32_t tswz(int row, int c16) {
    return (uint32_t)(row * 64 + ((c16 ^ ((row >> 1) & 3)) << 4));
}
__device__ __forceinline__ uint32_t h2(float a, float b) {
    __half2 h = __floats2half2_rn(a, b);
    return *(uint32_t*)&h;
}

// ---------------- prep (also zeroes g_sum) ----------------
__global__ void prep_all(const float* __restrict__ F, const float* __restrict__ CV,
                         const int* __restrict__ labels, const float* __restrict__ W) {
    const int b = blockIdx.x;
    const int tid = threadIdx.x;
    if (b < Cpad) {
        if (b < 16) {
            g_sum[b * 256 + tid] = 0.f;
        }
        const int c = b;
        uint32_t* w  = (uint32_t*)(g_W  + (size_t)c * Aa);
        uint32_t* w2 = (uint32_t*)(g_W2 + (size_t)c * Aa);
        if (c >= Cc) {
            for (int q = tid; q < Aa / 2; q += 256) { w[q] = 0u; w2[q] = 0u; }
            return;
        }
        const float2* wrow = (const float2*)(W + (size_t)c * Aa);
        for (int q = tid; q < Aa / 2; q += 256) {
            float2 v = wrow[q];
            w[q]  = h2(v.x, v.y);
            w2[q] = h2(v.x * v.x, v.y * v.y);
        }
    } else {
        const int n = b - Cpad;
        const int lab = load_label(labels, n);
        const float2* frow = (const float2*)(F  + (size_t)n * Aa);
        const float2* crow = (const float2*)(CV + (size_t)n * Aa);
        const float2* wrow = (const float2*)(W  + (size_t)lab * Aa);
        uint32_t* fh = (uint32_t*)(g_Fh + (size_t)n * Aa);
        uint32_t* cb = (uint32_t*)(g_C + (size_t)n * Aa);
        uint32_t* gb = (uint32_t*)(g_G + (size_t)n * Aa);

        float t3 = 0.f;
        for (int q = tid; q < Aa / 2; q += 256) {
            float2 f = frow[q];
            float2 cv = crow[q];
            float2 wy = wrow[q];
            fh[q] = h2(f.x, f.y);
            cb[q] = h2(cv.x, cv.y);
            float gx = cv.x * wy.x, gy = cv.y * wy.y;
            gb[q] = h2(-2.f * gx, -2.f * gy);
            t3 += gx * wy.x + gy * wy.y;
        }
        for (int o = 16; o; o >>= 1) t3 += __shfl_xor_sync(~0u, t3, o);
        __shared__ float ws[8];
        if ((tid & 31) == 0) ws[tid >> 5] = t3;
        __syncthreads();
        if (tid == 0) {
            float s = 0.f;
            for (int i = 0; i < 8; i++) s += ws[i];
            g_t3[n] = s;
        }
    }
}

// ---------------- fused triple GEMM + logsumexp epilogue ----------------
// accL = Fh.W -> logits ; accS = C.W2 + G.W -> sigma
// aug = logits + hr*(accS + t3); epilogue: atomic sumexp per row + label value.
__global__ __launch_bounds__(256, 1)
void gemm3h(const float* __restrict__ bias, const float* __restrict__ ratio_p,
            const int* __restrict__ labels, float* __restrict__ logits_out)
{
    extern __shared__ char smem[];
    const uint32_t sbase = smem_u32(smem);

    const int tid = threadIdx.x;
    const int lane = tid & 31;
    const int wid = tid >> 5;
    const int warp_m = wid >> 2;   // 0..1 : 64 rows
    const int warp_n = wid & 3;    // 0..3 : 32 cols
    const int bm = blockIdx.y * BM;
    const int bn = blockIdx.x * BN;

    const char* mp[NMATS];
    mp[0] = (const char*)g_Fh + (size_t)bm * 4096;
    mp[1] = (const char*)g_C  + (size_t)bm * 4096;
    mp[2] = (const char*)g_G  + (size_t)bm * 4096;
    mp[3] = (const char*)g_W  + (size_t)bn * 4096;
    mp[4] = (const char*)g_W2 + (size_t)bn * 4096;

    const int lrow = tid >> 2;          // 0..63
    const int lc16 = tid & 3;
    const uint32_t so0 = tswz(lrow, lc16);
    const uint32_t so1 = tswz(lrow + 64, lc16);
    const size_t go0 = (size_t)lrow * 4096 + lc16 * 16;
    const size_t go1 = go0 + (size_t)64 * 4096;

#define ISSUE(KT, S)                                                          \
    do {                                                                      \
        const size_t kb = (size_t)(KT) * 64;                                  \
        const uint32_t st_ = sbase + (uint32_t)(S) * STAGE_B;                 \
        _Pragma("unroll")                                                     \
        for (int m_ = 0; m_ < NMATS; m_++) {                                  \
            cp16(st_ + m_ * TILE_B + so0, mp[m_] + go0 + kb);                 \
            cp16(st_ + m_ * TILE_B + so1, mp[m_] + go1 + kb);                 \
        }                                                                     \
        cp_commit();                                                          \
    } while (0)

    float accL[4][4][4], accS[4][4][4];
#pragma unroll
    for (int i = 0; i < 4; i++)
#pragma unroll
        for (int j = 0; j < 4; j++)
#pragma unroll
            for (int e = 0; e < 4; e++) { accL[i][j][e] = 0.f; accS[i][j][e] = 0.f; }

    ISSUE(0, 0); ISSUE(1, 1);

    const int lr16 = lane & 15;
    const int lkhalf = lane >> 4;

    for (int kt = 0; kt < NKT; kt++) {
        if (kt == NKT - 1) { asm volatile("cp.async.wait_group 0;" ::: "memory"); }
        else               { asm volatile("cp.async.wait_group 1;" ::: "memory"); }
        __syncthreads();
        if (kt + 2 < NKT) ISSUE(kt + 2, (kt + 2) % NST);
        const uint32_t st = sbase + (uint32_t)(kt % NST) * STAGE_B;

#pragma unroll
        for (int k16 = 0; k16 < 2; k16++) {
            const int c16 = k16 * 2 + lkhalf;
            uint32_t bW[2][4], bW2[2][4];
#pragma unroll
            for (int np = 0; np < 2; np++) {
                const int r = warp_n * 32 + np * 16 + lr16;
                ldsm4(bW[np],  st + 3 * TILE_B + tswz(r, c16));
                ldsm4(bW2[np], st + 4 * TILE_B + tswz(r, c16));
            }
#pragma unroll
            for (int mt = 0; mt < 4; mt++) {
                uint32_t aF[4], aC[4], aG[4];
                const int r = warp_m * 64 + mt * 16 + lr16;
                ldsm4(aF, st + 0 * TILE_B + tswz(r, c16));
                ldsm4(aC, st + 1 * TILE_B + tswz(r, c16));
                ldsm4(aG, st + 2 * TILE_B + tswz(r, c16));
#pragma unroll
                for (int nt = 0; nt < 4; nt++) {
                    const int np = nt >> 1, sel = nt & 1;
                    const uint32_t w0 = bW[np][sel],  w1 = bW[np][sel + 2];
                    const uint32_t q0 = bW2[np][sel], q1 = bW2[np][sel + 2];
                    mma_f16(accL[mt][nt], aF, w0, w1);   // logits
                    mma_f16(accS[mt][nt], aC, q0, q1);   // t1
                    mma_f16(accS[mt][nt], aG, w0, w1);   // -2 t2
                }
            }
        }
    }
#undef ISSUE

    // ---------------- epilogue: logits store + fused logsumexp ----------------
    const float hr = 0.5f * (*ratio_p);
    const int r0 = lane >> 2;
    const int cq = (lane & 3) * 2;
#pragma unroll
    for (int mt = 0; mt < 4; mt++) {
        const int n0 = bm + warp_m * 64 + mt * 16 + r0;
        const int n1 = n0 + 8;
        const float t3a = g_t3[n0];
        const float t3b = g_t3[n1];
        const int lab0 = load_label(labels, n0);
        const int lab1 = load_label(labels, n1);
        float* lr0 = logits_out + (size_t)n0 * Cc;
        float* lr1 = logits_out + (size_t)n1 * Cc;
        float s0 = 0.f, s1 = 0.f;
#pragma unroll
        for (int nt = 0; nt < 4; nt++) {
            const int c = bn + warp_n * 32 + nt * 8 + cq;
            if (c < Cc) {
                const float2 bv = *(const float2*)(bias + c);
                const float* L = accL[mt][nt];
                const float* S = accS[mt][nt];
                const float l00 = L[0] + bv.x, l01 = L[1] + bv.y;
                const float l10 = L[2] + bv.x, l11 = L[3] + bv.y;
                lr0[c] = l00; lr0[c + 1] = l01;      // 4B-aligned base
                lr1[c] = l10; lr1[c + 1] = l11;
                const float a00 = l00 + hr * (S[0] + t3a);
                const float a01 = l01 + hr * (S[1] + t3a);
                const float a10 = l10 + hr * (S[2] + t3b);
                const float a11 = l11 + hr * (S[3] + t3b);
                s0 += expf(a00) + expf(a01);
                s1 += expf(a10) + expf(a11);
                if (c == lab0)     g_labv[n0] = a00;
                if (c + 1 == lab0) g_labv[n0] = a01;
                if (c == lab1)     g_labv[n1] = a10;
                if (c + 1 == lab1) g_labv[n1] = a11;
            }
        }
        s0 += __shfl_xor_sync(~0u, s0, 1); s0 += __shfl_xor_sync(~0u, s0, 2);
        s1 += __shfl_xor_sync(~0u, s1, 1); s1 += __shfl_xor_sync(~0u, s1, 2);
        if ((lane & 3) == 0) {
            atomicAdd(&g_sum[n0], s0);
            atomicAdd(&g_sum[n1], s1);
        }
    }
}

// ---------------- final: nll = log(sum) - labv ; mean ----------------
__global__ void finalize_kernel(float* __restrict__ out) {
    const int tid = threadIdx.x;
    float s = 0.f;
    for (int i = tid; i < Nn; i += 1024)
        s += logf(g_sum[i]) - g_labv[i];
    for (int o = 16; o; o >>= 1) s += __shfl_xor_sync(~0u, s, o);
    __shared__ float ws[32];
    if ((tid & 31) == 0) ws[tid >> 5] = s;
    __syncthreads();
    if (tid < 32) {
        float v = ws[tid];
        for (int o = 16; o; o >>= 1) v += __shfl_xor_sync(~0u, v, o);
        if (tid == 0) out[0] = v / (float)Nn;
    }
}

// ---------------- launch ----------------
extern "C" void kernel_launch(void* const* d_in, const int* in_sizes, int n_in,
                              void* d_out, int out_size) {
    const float* F      = (const float*)d_in[0];
    const int*   labels = (const int*)d_in[1];
    const float* CV     = (const float*)d_in[2];
    const float* ratio  = (const float*)d_in[3];
    const float* W      = (const float*)d_in[4];
    const float* bias   = (const float*)d_in[5];
    float* out = (float*)d_out;

    long long logits_off = (long long)out_size - (long long)Nn * Cc;
    if (logits_off < 0) logits_off = 0;
    float* logits_out = out + logits_off;

    static bool attr_set = false;
    if (!attr_set) {
        cudaFuncSetAttribute(gemm3h, cudaFuncAttributeMaxDynamicSharedMemorySize, SMEM_DYN);
        attr_set = true;
    }

    prep_all<<<Cpad + Nn, 256>>>(F, CV, labels, W);

    dim3 grid(Cpad / BN, Nn / BM);   // 8 x 32 = 256 CTAs
    gemm3h<<<grid, 256, SMEM_DYN>>>(bias, ratio, labels, logits_out);

    finalize_kernel<<<1, 1024>>>(out);
}